// round 4
// baseline (speedup 1.0000x reference)
#include <cuda_runtime.h>

// Kannala-Brandt fisheye round-trip, packed-f32x2 version.
// All elementwise math runs two points per instruction via PTX fma/mul/add.rn.f32x2
// (the only way to emit FFMA2 on sm_103a). MUFU ops (rsqrt, sin) stay scalar.
//
// Numerics (vs reference, tolerance 1e-3):
//  * Newton with rcp(fp) ~= (2-fp): 2 iterations reach the fp32 fixed point.
//  * theta = t (drops the O(eps) atan2 correction, ~1e-7 rel effect).
//  * 1/(ru+eps) -> rsqrt(mx^2+my^2+1e-30): <=1e-5 rel effect, NaN-safe at center.

#define CX 640.0f
#define CY 480.0f
#define EPS 1e-5f

typedef unsigned long long u64;

__device__ __forceinline__ u64 pk2(float lo, float hi) {
    u64 r; asm("mov.b64 %0, {%1, %2};" : "=l"(r) : "f"(lo), "f"(hi)); return r;
}
__device__ __forceinline__ void upk2(u64 v, float& lo, float& hi) {
    asm("mov.b64 {%0, %1}, %2;" : "=f"(lo), "=f"(hi) : "l"(v));
}
__device__ __forceinline__ u64 fma2(u64 a, u64 b, u64 c) {
    u64 d; asm("fma.rn.f32x2 %0, %1, %2, %3;" : "=l"(d) : "l"(a), "l"(b), "l"(c)); return d;
}
__device__ __forceinline__ u64 mul2(u64 a, u64 b) {
    u64 d; asm("mul.rn.f32x2 %0, %1, %2;" : "=l"(d) : "l"(a), "l"(b)); return d;
}
__device__ __forceinline__ u64 add2(u64 a, u64 b) {
    u64 d; asm("add.rn.f32x2 %0, %1, %2;" : "=l"(d) : "l"(a), "l"(b)); return d;
}

struct KP {
    u64 K0, K1, K2, K3, K4;        // forward poly coeffs (broadcast)
    u64 D1, D2, D3, D4, K0E;       // derivative coeffs, k0+eps
    u64 RFX, RFY;                  // 1/fx, 1/fy broadcast
    u64 NCX, NCY, CX2, CY2;        // -center / +center broadcast
    u64 TINY, NEG1, NTWO;
};

// Process two points (x0,y0),(x1,y1) -> packed u2, v2.
__device__ __forceinline__ void kb_pair(float x0, float y0, float x1, float y1,
                                        const KP& P, u64& u2, u64& v2)
{
    u64 dx2 = add2(pk2(x0, x1), P.NCX);
    u64 dy2 = add2(pk2(y0, y1), P.NCY);
    u64 mx2 = mul2(dx2, P.RFX);
    u64 my2 = mul2(dy2, P.RFY);
    u64 q2  = fma2(mx2, mx2, fma2(my2, my2, P.TINY));

    float q0, q1; upk2(q2, q0, q1);
    u64 ir2 = pk2(rsqrtf(q0), rsqrtf(q1));
    u64 ru2 = mul2(q2, ir2);
    u64 nru2 = mul2(ru2, P.NEG1);

    // quasi-Newton, 2 iterations
    u64 t2 = ru2;
#pragma unroll
    for (int it = 0; it < 2; ++it) {
        u64 p  = fma2(P.K4, t2, P.K3);
        p      = fma2(p, t2, P.K2);
        p      = fma2(p, t2, P.K1);
        p      = fma2(p, t2, P.K0);
        u64 r  = fma2(p, t2, nru2);             // f(t) - ru
        u64 fp = fma2(P.D4, t2, P.D3);
        fp     = fma2(fp, t2, P.D2);
        fp     = fma2(fp, t2, P.D1);
        fp     = fma2(fp, t2, P.K0E);
        // t -= r*(2-fp)  ==  t + r*fp - 2r
        t2 = fma2(P.NTWO, r, fma2(r, fp, t2));
    }

    // forward distortion d(theta=t)
    u64 d2 = fma2(P.K4, t2, P.K3);
    d2     = fma2(d2, t2, P.K2);
    d2     = fma2(d2, t2, P.K1);
    d2     = fma2(d2, t2, P.K0);

    float t0, t1; upk2(t2, t0, t1);
    u64 s2 = pk2(__sinf(t0), __sinf(t1));

    u64 w2 = mul2(mul2(d2, s2), ir2);
    u2 = fma2(w2, dx2, P.CX2);
    v2 = fma2(w2, dy2, P.CY2);
}

__global__ void kb_roundtrip_kernel(const float4* __restrict__ in4,
                                    const float2* __restrict__ in2,
                                    const float*  __restrict__ kvec,
                                    const float*  __restrict__ fx_p,
                                    const float*  __restrict__ fy_p,
                                    float4*       __restrict__ out4,
                                    float2*       __restrict__ out2,
                                    int n_quads, int n_tail_pts)
{
    int i = blockIdx.x * blockDim.x + threadIdx.x;

    float k0 = __ldg(&kvec[0]), k1 = __ldg(&kvec[1]), k2 = __ldg(&kvec[2]);
    float k3 = __ldg(&kvec[3]), k4 = __ldg(&kvec[4]);
    float rfx = __fdividef(1.0f, __ldg(fx_p));
    float rfy = __fdividef(1.0f, __ldg(fy_p));

    KP P;
    P.K0 = pk2(k0, k0); P.K1 = pk2(k1, k1); P.K2 = pk2(k2, k2);
    P.K3 = pk2(k3, k3); P.K4 = pk2(k4, k4);
    P.D1 = pk2(2*k1, 2*k1); P.D2 = pk2(3*k2, 3*k2);
    P.D3 = pk2(4*k3, 4*k3); P.D4 = pk2(5*k4, 5*k4);
    P.K0E = pk2(k0 + EPS, k0 + EPS);
    P.RFX = pk2(rfx, rfx); P.RFY = pk2(rfy, rfy);
    P.NCX = pk2(-CX, -CX); P.NCY = pk2(-CY, -CY);
    P.CX2 = pk2(CX, CX);   P.CY2 = pk2(CY, CY);
    P.TINY = pk2(1e-30f, 1e-30f);
    P.NEG1 = pk2(-1.0f, -1.0f);
    P.NTWO = pk2(-2.0f, -2.0f);

    if (i < n_quads) {
        float4 a = in4[2 * i];
        float4 b = in4[2 * i + 1];

        u64 ua, va, ub, vb;
        kb_pair(a.x, a.y, a.z, a.w, P, ua, va);
        kb_pair(b.x, b.y, b.z, b.w, P, ub, vb);

        float u0, u1, v0, v1;
        upk2(ua, u0, u1); upk2(va, v0, v1);
        out4[2 * i] = make_float4(u0, v0, u1, v1);
        upk2(ub, u0, u1); upk2(vb, v0, v1);
        out4[2 * i + 1] = make_float4(u0, v0, u1, v1);
    }
    // tail (none for N=4194304)
    if (n_tail_pts && i == 0) {
        for (int j = 0; j < n_tail_pts; ++j) {
            int idx = 4 * n_quads + j;
            float2 p = in2[idx];
            u64 u2, v2;
            kb_pair(p.x, p.y, p.x, p.y, P, u2, v2);
            float u0, u1, v0, v1;
            upk2(u2, u0, u1); upk2(v2, v0, v1);
            out2[idx] = make_float2(u0, v0);
        }
    }
}

extern "C" void kernel_launch(void* const* d_in, const int* in_sizes, int n_in,
                              void* d_out, int out_size)
{
    const float* uv = (const float*)d_in[0];
    const float* kv = (const float*)d_in[1];
    const float* fx = (const float*)d_in[2];
    const float* fy = (const float*)d_in[3];

    int n       = in_sizes[0] / 2;
    int n_quads = n / 4;
    int n_tail  = n - 4 * n_quads;

    const int threads = 256;
    int work   = n_quads > 0 ? n_quads : 1;
    int blocks = (work + threads - 1) / threads;

    kb_roundtrip_kernel<<<blocks, threads>>>(
        (const float4*)uv, (const float2*)uv, kv, fx, fy,
        (float4*)d_out, (float2*)d_out, n_quads, n_tail);
}